// round 7
// baseline (speedup 1.0000x reference)
#include <cuda_runtime.h>
#include <cuda_bf16.h>
#include <cstdint>
#include <cstddef>

// ---------------------------------------------------------------------------
// Scratch (no allocations allowed -> __device__ globals)
// ---------------------------------------------------------------------------
__device__ float g_h[1024 * 256];     // h = x @ W_in^T + b_in          (1024 x 256)
__device__ float g_pab[1024 * 512];   // [pa | pb], pa has +b1 folded   (1024 x 512)
__device__ float g_W2t[256 * 64];     // W2 transposed: W2t[g*64 + e] = W2[e*256 + g]

// ---------------------------------------------------------------------------
// f32x2 helpers (Blackwell packed fp32 pair FMA -- 2x FFMA throughput)
// ---------------------------------------------------------------------------
#define DINL __device__ __forceinline__

DINL unsigned long long f2_pack(float lo, float hi) {
    unsigned long long r;
    asm("mov.b64 %0, {%1, %2};" : "=l"(r) : "f"(lo), "f"(hi));
    return r;
}
DINL void f2_unpack(unsigned long long v, float& lo, float& hi) {
    asm("mov.b64 {%0, %1}, %2;" : "=f"(lo), "=f"(hi) : "l"(v));
}
DINL unsigned long long f2_fma(unsigned long long a, unsigned long long b,
                               unsigned long long c) {
    unsigned long long d;
    asm("fma.rn.f32x2 %0, %1, %2, %3;" : "=l"(d) : "l"(a), "l"(b), "l"(c));
    return d;
}

// ---------------------------------------------------------------------------
// Generic NT GEMM: C[m][n] = sum_k A[m*K+k] * B'[n][k] + (n<bias_n ? bias[n]:0)
//   B'[n][k] = B[(n & 255)*ldb + (n>>8)*hi_off + k]
//   gemm1 (h):   ldb=256, hi_off=0    -> B'[n][k] = W_in[n*256+k]
//   gemm2 (pab): ldb=512, hi_off=256  -> n<256: W1[n][k] (pa),  n>=256: W1[n-256][256+k] (pb)
// BM=BN=64, BK=16, 256 threads, 4x4 microtile. M,N,K all divisible.
// ---------------------------------------------------------------------------
__global__ __launch_bounds__(256) void gemm_nt_kernel(
    const float* __restrict__ A, const float* __restrict__ B,
    const float* __restrict__ bias, float* __restrict__ C,
    int M, int N, int K, int ldb, int hi_off, int bias_n)
{
    __shared__ float As[64][17];
    __shared__ float Bs[64][17];
    const int t  = threadIdx.x;
    const int n0 = blockIdx.x * 64;
    const int m0 = blockIdx.y * 64;
    const int lr = t >> 2;        // 0..63 load row
    const int lq = (t & 3) * 4;   // 0,4,8,12 k-quad
    const int ty = t >> 4;        // 0..15
    const int tx = t & 15;        // 0..15

    float acc[4][4];
#pragma unroll
    for (int i = 0; i < 4; ++i)
#pragma unroll
        for (int j = 0; j < 4; ++j) acc[i][j] = 0.0f;

    for (int k0 = 0; k0 < K; k0 += 16) {
        float4 av = *(const float4*)(A + (size_t)(m0 + lr) * K + k0 + lq);
        const int nr = n0 + lr;
        float4 bv = *(const float4*)(B + (size_t)(nr & 255) * ldb
                                       + (size_t)(nr >> 8) * hi_off + k0 + lq);
        __syncthreads();
        As[lr][lq + 0] = av.x; As[lr][lq + 1] = av.y;
        As[lr][lq + 2] = av.z; As[lr][lq + 3] = av.w;
        Bs[lr][lq + 0] = bv.x; Bs[lr][lq + 1] = bv.y;
        Bs[lr][lq + 2] = bv.z; Bs[lr][lq + 3] = bv.w;
        __syncthreads();
#pragma unroll
        for (int k = 0; k < 16; ++k) {
            float a[4], bb[4];
#pragma unroll
            for (int i = 0; i < 4; ++i) a[i] = As[ty * 4 + i][k];
#pragma unroll
            for (int j = 0; j < 4; ++j) bb[j] = Bs[tx * 4 + j][k];
#pragma unroll
            for (int i = 0; i < 4; ++i)
#pragma unroll
                for (int j = 0; j < 4; ++j) acc[i][j] = fmaf(a[i], bb[j], acc[i][j]);
        }
    }

#pragma unroll
    for (int j = 0; j < 4; ++j) {
        const int n = n0 + tx * 4 + j;
        const float bz = (n < bias_n) ? bias[n] : 0.0f;
#pragma unroll
        for (int i = 0; i < 4; ++i)
            C[(size_t)(m0 + ty * 4 + i) * N + n] = acc[i][j] + bz;
    }
}

// ---------------------------------------------------------------------------
// W2 transpose: W2t[g*64 + e] = W2[e*256 + g]   (16384 elems)
// ---------------------------------------------------------------------------
__global__ void w2t_kernel(const float* __restrict__ W2, float* __restrict__ W2t)
{
    const int idx = blockIdx.x * 256 + threadIdx.x;   // grid 64 x 256
    const int e = idx >> 8;
    const int g = idx & 255;
    W2t[g * 64 + e] = W2[idx];
}

// ---------------------------------------------------------------------------
// Main fused kernel.
// Per CTA: 16 i x 16 j = 256 pairs, all 64 e.  K=256 in 16 tiles of BK=16.
// A-tile As[k][pair] generated on the fly: silu(pa[i][g] + pb[j][g]) (b1 folded
// into pa).  W2^T kept k-major in smem.  256 threads as 32 pair-groups x 8
// e-threads; 8x8 microtile with f32x2 packed accumulation (pairs packed along
// the pair/M axis so the A-fragment loads are natural LDS.64).
// smem: 16384 (W2t) + 2*16*260 (As) floats = 98816 B -> 2 CTAs/SM.
// ---------------------------------------------------------------------------
#define PAP 260   // As pair-pitch: k*260*4B mod 128 = 16k*... -> conflict-benign, 16B-multiple

__global__ __launch_bounds__(256, 2) void edge_main_kernel(
    const float* __restrict__ pab, const float* __restrict__ W2t_g,
    const float* __restrict__ b2, float* __restrict__ out)
{
    extern __shared__ float smem[];
    float* W2t = smem;                 // [k*64 + e], 16384 floats
    float* Asm = smem + 16384;         // [buf][k*PAP + pair], 2*16*260 floats

    const int t = threadIdx.x;
    const int iTile = blockIdx.x;      // 0..15
    const int jTile = blockIdx.y;      // 0..15
    const int b     = blockIdx.z;      // 0..3

    // ---- load W2^T into smem (coalesced float4) ----
    {
        const float4* src = (const float4*)W2t_g;
        float4* dst = (float4*)W2t;
#pragma unroll
        for (int i = 0; i < 16; ++i) dst[t + i * 256] = src[t + i * 256];
    }

    const float* paBase = pab + (size_t)(b * 256 + iTile * 16) * 512;        // pa[i][g]
    const float* pbBase = pab + (size_t)(b * 256 + jTile * 16) * 512 + 256;  // pb[j][g]

    // gen-phase mapping: thread (gk = k-in-tile, gi = local i) fills 16 j's
    const int gk = t & 15;
    const int gi = t >> 4;
    // compute-phase mapping: 8 consecutive pairs x 8 e per thread
    const int p0 = (t >> 3) * 8;       // pair base (0..248)
    const int e0 = (t & 7) * 8;        // e base (0..56)

    unsigned long long acc[4][8];
#pragma unroll
    for (int i = 0; i < 4; ++i)
#pragma unroll
        for (int j = 0; j < 8; ++j) acc[i][j] = 0ull;

    // ---- A-tile generator: As[buf][k][pair] = silu(pa + pb) ----
    auto GEN = [&](int buf, int kt) {
        const int g = kt * 16 + gk;
        const float pav = paBase[gi * 512 + g];
        float* dst = Asm + buf * (16 * PAP) + gk * PAP + gi * 16;
#pragma unroll
        for (int j = 0; j < 16; ++j) {
            const float zv = pav + pbBase[j * 512 + g];
            const float ev = __expf(-zv);
            dst[j] = __fdividef(zv, 1.0f + ev);     // z * sigmoid(z)
        }
    };

    GEN(0, 0);
    __syncthreads();   // W2t + first A-tile ready

#pragma unroll 1
    for (int kt = 0; kt < 16; ++kt) {
        if (kt < 15) GEN((kt + 1) & 1, kt + 1);     // prefetch next tile (other buffer)

        const float* Ab = Asm + (kt & 1) * (16 * PAP);
#pragma unroll
        for (int k = 0; k < 16; ++k) {
            const float* ar = Ab + k * PAP + p0;
            unsigned long long a2[4];
#pragma unroll
            for (int i = 0; i < 4; ++i)
                a2[i] = *(const unsigned long long*)(ar + 2 * i);   // LDS.64: 2 pairs

            const float4* wr = (const float4*)(W2t + (kt * 16 + k) * 64 + e0);
            const float4 w0 = wr[0];
            const float4 w1 = wr[1];
            unsigned long long bd[8];
            bd[0] = f2_pack(w0.x, w0.x); bd[1] = f2_pack(w0.y, w0.y);
            bd[2] = f2_pack(w0.z, w0.z); bd[3] = f2_pack(w0.w, w0.w);
            bd[4] = f2_pack(w1.x, w1.x); bd[5] = f2_pack(w1.y, w1.y);
            bd[6] = f2_pack(w1.z, w1.z); bd[7] = f2_pack(w1.w, w1.w);

#pragma unroll
            for (int i = 0; i < 4; ++i)
#pragma unroll
                for (int j = 0; j < 8; ++j)
                    acc[i][j] = f2_fma(a2[i], bd[j], acc[i][j]);
        }
        __syncthreads();   // protect buffer reuse by next GEN
    }

    // ---- epilogue: + b2, write out[b][i][j][e] ----
    const float4 c0 = *(const float4*)(b2 + e0);
    const float4 c1 = *(const float4*)(b2 + e0 + 4);

#pragma unroll
    for (int i2 = 0; i2 < 4; ++i2) {
        float lo[8], hi[8];
#pragma unroll
        for (int j = 0; j < 8; ++j) f2_unpack(acc[i2][j], lo[j], hi[j]);

        {   // low half of the packed pair -> pair p0 + 2*i2
            const int pair = p0 + 2 * i2;
            const int iL = pair >> 4, jL = pair & 15;
            const size_t row = (size_t)(b * 256 + iTile * 16 + iL) * 256
                             + (jTile * 16 + jL);
            float* op = out + row * 64 + e0;
            *(float4*)op       = make_float4(lo[0] + c0.x, lo[1] + c0.y,
                                             lo[2] + c0.z, lo[3] + c0.w);
            *(float4*)(op + 4) = make_float4(lo[4] + c1.x, lo[5] + c1.y,
                                             lo[6] + c1.z, lo[7] + c1.w);
        }
        {   // high half -> pair p0 + 2*i2 + 1
            const int pair = p0 + 2 * i2 + 1;
            const int iL = pair >> 4, jL = pair & 15;
            const size_t row = (size_t)(b * 256 + iTile * 16 + iL) * 256
                             + (jTile * 16 + jL);
            float* op = out + row * 64 + e0;
            *(float4*)op       = make_float4(hi[0] + c0.x, hi[1] + c0.y,
                                             hi[2] + c0.z, hi[3] + c0.w);
            *(float4*)(op + 4) = make_float4(hi[4] + c1.x, hi[5] + c1.y,
                                             hi[6] + c1.z, hi[7] + c1.w);
        }
    }
}

// ---------------------------------------------------------------------------
// Launch
// ---------------------------------------------------------------------------
extern "C" void kernel_launch(void* const* d_in, const int* in_sizes, int n_in,
                              void* d_out, int out_size)
{
    (void)in_sizes; (void)n_in; (void)out_size;
    const float* x    = (const float*)d_in[0];   // (4,256,256)
    const float* W_in = (const float*)d_in[1];   // (256,256)
    const float* b_in = (const float*)d_in[2];   // (256,)
    const float* W1   = (const float*)d_in[3];   // (256,512)
    const float* b1   = (const float*)d_in[4];   // (256,)
    const float* W2   = (const float*)d_in[5];   // (64,256)
    const float* b2   = (const float*)d_in[6];   // (64,)
    float* out = (float*)d_out;                  // (4,256,256,64) fp32

    float *hp = nullptr, *pabp = nullptr, *w2tp = nullptr;
    cudaGetSymbolAddress((void**)&hp,   g_h);
    cudaGetSymbolAddress((void**)&pabp, g_pab);
    cudaGetSymbolAddress((void**)&w2tp, g_W2t);

    // h = x @ W_in^T + b_in
    gemm_nt_kernel<<<dim3(4, 16), 256>>>(x, W_in, b_in, hp,
                                         1024, 256, 256, 256, 0, 256);
    // [pa | pb] = h @ [Wa^T | Wb^T], b1 folded into pa
    gemm_nt_kernel<<<dim3(8, 16), 256>>>(hp, W1, b1, pabp,
                                         1024, 512, 256, 512, 256, 256);
    // W2 transpose for k-major smem staging
    w2t_kernel<<<64, 256>>>(W2, w2tp);

    const int smem_bytes = (16384 + 2 * 16 * PAP) * 4;   // 98816 B
    cudaFuncSetAttribute(edge_main_kernel,
                         cudaFuncAttributeMaxDynamicSharedMemorySize, smem_bytes);
    edge_main_kernel<<<dim3(16, 16, 4), 256, smem_bytes>>>(pabp, w2tp, b2, out);
}

// round 9
// speedup vs baseline: 1.6489x; 1.6489x over previous
#include <cuda_runtime.h>
#include <cuda_bf16.h>
#include <cstdint>
#include <cstddef>

// ---------------------------------------------------------------------------
// Scratch (no allocations allowed -> __device__ globals)
// ---------------------------------------------------------------------------
__device__ float g_h[1024 * 256];              // h = x @ W_in^T + b_in
__device__ float g_pab[1024 * 512];            // [pa | pb], b1 folded into pa
__device__ __nv_bfloat16 g_W2hi[64 * 256];     // bf16 split of W2, natural [e][g]
__device__ __nv_bfloat16 g_W2lo[64 * 256];

#define DINL __device__ __forceinline__

// ---------------------------------------------------------------------------
// PTX helpers (sm_80-era instructions only; harness builds plain compute_103)
// ---------------------------------------------------------------------------
DINL uint32_t smem_u32(const void* p) {
    uint32_t a;
    asm("{ .reg .u64 t; cvta.to.shared.u64 t, %1; cvt.u32.u64 %0, t; }"
        : "=r"(a) : "l"(p));
    return a;
}
DINL void ldsm_x4(uint32_t& r0, uint32_t& r1, uint32_t& r2, uint32_t& r3,
                  uint32_t addr) {
    asm volatile("ldmatrix.sync.aligned.m8n8.x4.shared.b16 {%0,%1,%2,%3}, [%4];"
                 : "=r"(r0), "=r"(r1), "=r"(r2), "=r"(r3) : "r"(addr));
}
DINL void mma16816(float* c, const uint32_t* a, uint32_t b0, uint32_t b1) {
    asm volatile(
        "mma.sync.aligned.m16n8k16.row.col.f32.bf16.bf16.f32 "
        "{%0,%1,%2,%3}, {%4,%5,%6,%7}, {%8,%9}, {%0,%1,%2,%3};"
        : "+f"(c[0]), "+f"(c[1]), "+f"(c[2]), "+f"(c[3])
        : "r"(a[0]), "r"(a[1]), "r"(a[2]), "r"(a[3]), "r"(b0), "r"(b1));
}
DINL float silu_f(float z) {
    const float e = __expf(-z);
    return __fdividef(z, 1.0f + e);
}
DINL uint32_t pack_bf(__nv_bfloat16 a, __nv_bfloat16 b) {
    return (uint32_t)__bfloat16_as_ushort(a)
         | ((uint32_t)__bfloat16_as_ushort(b) << 16);
}

// ---------------------------------------------------------------------------
// SMEM layout (bytes)
//   W2 tiles:  [e][g] bf16, 64 rows x 512B data, pitch 528  (ldmatrix: 4r%32 banks, conflict-free)
//   pa/pb:     fp32 rows pitch 1040 (260 floats)
//   A tiles:   [pair][k32] bf16, 128 rows x 64B data, pitch 80 (20r%32 banks, conflict-free)
// ---------------------------------------------------------------------------
static constexpr int W2_PITCH = 528;
static constexpr int PAB_PITCH = 1040;
static constexpr int A_PITCH = 80;
static constexpr int OFF_W2HI = 0;                       // 64*528 = 33792
static constexpr int OFF_W2LO = OFF_W2HI + 64 * W2_PITCH;
static constexpr int OFF_PA   = OFF_W2LO + 64 * W2_PITCH;    // 8 rows
static constexpr int OFF_PB   = OFF_PA + 8 * PAB_PITCH;      // 16 rows
static constexpr int OFF_AHI  = OFF_PB + 16 * PAB_PITCH;     // 128*80 = 10240
static constexpr int OFF_ALO  = OFF_AHI + 128 * A_PITCH;
static constexpr int SMEM_TOTAL = OFF_ALO + 128 * A_PITCH;   // 113024 B

// ---------------------------------------------------------------------------
// Prologue GEMM (validated in R7): C = A @ B'^T (+bias)
// ---------------------------------------------------------------------------
__global__ __launch_bounds__(256) void gemm_nt_kernel(
    const float* __restrict__ A, const float* __restrict__ B,
    const float* __restrict__ bias, float* __restrict__ C,
    int M, int N, int K, int ldb, int hi_off, int bias_n)
{
    __shared__ float As[64][17];
    __shared__ float Bs[64][17];
    const int t  = threadIdx.x;
    const int n0 = blockIdx.x * 64;
    const int m0 = blockIdx.y * 64;
    const int lr = t >> 2;
    const int lq = (t & 3) * 4;
    const int ty = t >> 4;
    const int tx = t & 15;

    float acc[4][4];
#pragma unroll
    for (int i = 0; i < 4; ++i)
#pragma unroll
        for (int j = 0; j < 4; ++j) acc[i][j] = 0.0f;

    for (int k0 = 0; k0 < K; k0 += 16) {
        float4 av = *(const float4*)(A + (size_t)(m0 + lr) * K + k0 + lq);
        const int nr = n0 + lr;
        float4 bv = *(const float4*)(B + (size_t)(nr & 255) * ldb
                                       + (size_t)(nr >> 8) * hi_off + k0 + lq);
        __syncthreads();
        As[lr][lq + 0] = av.x; As[lr][lq + 1] = av.y;
        As[lr][lq + 2] = av.z; As[lr][lq + 3] = av.w;
        Bs[lr][lq + 0] = bv.x; Bs[lr][lq + 1] = bv.y;
        Bs[lr][lq + 2] = bv.z; Bs[lr][lq + 3] = bv.w;
        __syncthreads();
#pragma unroll
        for (int k = 0; k < 16; ++k) {
            float a[4], bb[4];
#pragma unroll
            for (int i = 0; i < 4; ++i) a[i] = As[ty * 4 + i][k];
#pragma unroll
            for (int j = 0; j < 4; ++j) bb[j] = Bs[tx * 4 + j][k];
#pragma unroll
            for (int i = 0; i < 4; ++i)
#pragma unroll
                for (int j = 0; j < 4; ++j) acc[i][j] = fmaf(a[i], bb[j], acc[i][j]);
        }
    }
#pragma unroll
    for (int j = 0; j < 4; ++j) {
        const int n = n0 + tx * 4 + j;
        const float bz = (n < bias_n) ? bias[n] : 0.0f;
#pragma unroll
        for (int i = 0; i < 4; ++i)
            C[(size_t)(m0 + ty * 4 + i) * N + n] = acc[i][j] + bz;
    }
}

// ---------------------------------------------------------------------------
// W2 hi/lo bf16 split (keeps natural [e][g] layout)
// ---------------------------------------------------------------------------
__global__ void w2split_kernel(const float* __restrict__ W2,
                               __nv_bfloat16* __restrict__ hi,
                               __nv_bfloat16* __restrict__ lo)
{
    const int idx = blockIdx.x * 256 + threadIdx.x;   // 16384
    const float w = W2[idx];
    const __nv_bfloat16 h = __float2bfloat16(w);
    hi[idx] = h;
    lo[idx] = __float2bfloat16(w - __bfloat162float(h));
}

// ---------------------------------------------------------------------------
// Main fused kernel: SiLU gen (bf16 hi/lo) -> mma.sync bf16 x3 passes -> store.
// Per CTA: 128 pairs (8i x 16j) x 64 e, K=256 in 8 chunks of 32.
// 8 warps; warp w owns m16 = pairs [16w,16w+16), all 64 e (8 n8-blocks).
// ---------------------------------------------------------------------------
__global__ __launch_bounds__(256, 2) void edge_main_mma(
    const float* __restrict__ pab,
    const __nv_bfloat16* __restrict__ W2hi_g,
    const __nv_bfloat16* __restrict__ W2lo_g,
    const float* __restrict__ b2, float* __restrict__ out)
{
    extern __shared__ __align__(16) char smem[];
    const uint32_t sb = smem_u32(smem);
    const int t = threadIdx.x;
    const int w = t >> 5;
    const int l = t & 31;
    const int i0 = blockIdx.x * 8;
    const int j0 = blockIdx.y * 16;
    const int b  = blockIdx.z;

    // ---- stage W2 hi/lo into [e][g] pitch-528 tiles ----
    {
        const uint4* hs = (const uint4*)W2hi_g;   // 2048 uint4 each
        const uint4* ls = (const uint4*)W2lo_g;
#pragma unroll
        for (int i = 0; i < 8; ++i) {
            const int idx = t + i * 256;
            const int row = idx >> 5, c = idx & 31;
            *(uint4*)(smem + OFF_W2HI + row * W2_PITCH + c * 16) = hs[idx];
            *(uint4*)(smem + OFF_W2LO + row * W2_PITCH + c * 16) = ls[idx];
        }
    }
    // ---- stage pa (8 x 256 f32) and pb (16 x 256 f32) ----
#pragma unroll
    for (int i = 0; i < 2; ++i) {
        const int idx = t + i * 256, r = idx >> 6, c4 = idx & 63;
        ((float4*)(smem + OFF_PA + r * PAB_PITCH))[c4] =
            ((const float4*)(pab + (size_t)(b * 256 + i0 + r) * 512))[c4];
    }
#pragma unroll
    for (int i = 0; i < 4; ++i) {
        const int idx = t + i * 256, r = idx >> 6, c4 = idx & 63;
        ((float4*)(smem + OFF_PB + r * PAB_PITCH))[c4] =
            ((const float4*)(pab + (size_t)(b * 256 + j0 + r) * 512 + 256))[c4];
    }

    // gen mapping: pair p = t&127, kh = t>>7 picks which 16 of the 32 k's
    const int p  = t & 127;
    const int kh = t >> 7;
    const float* paR = (const float*)(smem + OFF_PA + (p >> 4) * PAB_PITCH) + kh * 16;
    const float* pbR = (const float*)(smem + OFF_PB + (p & 15) * PAB_PITCH) + kh * 16;
    char* ahiW = smem + OFF_AHI + p * A_PITCH + kh * 32;
    char* aloW = smem + OFF_ALO + p * A_PITCH + kh * 32;

    // ldmatrix base addresses (lane-dependent), computed once
    const int grp = l >> 3;                       // 0..3
    const uint32_t aRowOff =
        (uint32_t)((w * 16 + (grp & 1) * 8 + (l & 7)) * A_PITCH + (grp >> 1) * 16);
    const uint32_t aHiAddr = sb + OFF_AHI + aRowOff;
    const uint32_t aLoAddr = sb + OFF_ALO + aRowOff;
    // B: rows = e, x4 covers (e0-7,kLo),(e0-7,kHi),(e8-15,kLo),(e8-15,kHi)
    const uint32_t bRowPart =
        (uint32_t)(((grp >> 1) * 8 + (l & 7)) * W2_PITCH + (grp & 1) * 16);
    const uint32_t bHiBase = sb + OFF_W2HI + bRowPart;
    const uint32_t bLoBase = sb + OFF_W2LO + bRowPart;

    float acc[8][4];
#pragma unroll
    for (int n = 0; n < 8; ++n)
#pragma unroll
        for (int q = 0; q < 4; ++q) acc[n][q] = 0.0f;

    __syncthreads();

    for (int c = 0; c < 8; ++c) {
        // ---- gen: 16 silu values -> bf16 hi/lo into A tile ----
        {
            const float4* A4 = (const float4*)(paR + c * 32);
            const float4* B4 = (const float4*)(pbR + c * 32);
            uint32_t hiu[8], lou[8];
#pragma unroll
            for (int q = 0; q < 4; ++q) {
                const float4 av = A4[q];
                const float4 bv = B4[q];
                const float s0 = silu_f(av.x + bv.x);
                const float s1 = silu_f(av.y + bv.y);
                const float s2 = silu_f(av.z + bv.z);
                const float s3 = silu_f(av.w + bv.w);
                const __nv_bfloat16 h0 = __float2bfloat16(s0);
                const __nv_bfloat16 h1 = __float2bfloat16(s1);
                const __nv_bfloat16 h2 = __float2bfloat16(s2);
                const __nv_bfloat16 h3 = __float2bfloat16(s3);
                hiu[2 * q]     = pack_bf(h0, h1);
                hiu[2 * q + 1] = pack_bf(h2, h3);
                lou[2 * q]     = pack_bf(
                    __float2bfloat16(s0 - __bfloat162float(h0)),
                    __float2bfloat16(s1 - __bfloat162float(h1)));
                lou[2 * q + 1] = pack_bf(
                    __float2bfloat16(s2 - __bfloat162float(h2)),
                    __float2bfloat16(s3 - __bfloat162float(h3)));
            }
            *(uint4*)(ahiW)      = make_uint4(hiu[0], hiu[1], hiu[2], hiu[3]);
            *(uint4*)(ahiW + 16) = make_uint4(hiu[4], hiu[5], hiu[6], hiu[7]);
            *(uint4*)(aloW)      = make_uint4(lou[0], lou[1], lou[2], lou[3]);
            *(uint4*)(aloW + 16) = make_uint4(lou[4], lou[5], lou[6], lou[7]);
        }
        __syncthreads();   // A tile ready

        // ---- mma: 2 k16 slices x 8 n8-blocks x 3 passes ----
#pragma unroll
        for (int s = 0; s < 2; ++s) {
            uint32_t ah[4], al[4];
            ldsm_x4(ah[0], ah[1], ah[2], ah[3], aHiAddr + s * 32);
            ldsm_x4(al[0], al[1], al[2], al[3], aLoAddr + s * 32);
            const uint32_t kOff = (uint32_t)((c * 32 + s * 16) * 2);  // byte col in W2 row
#pragma unroll
            for (int nb = 0; nb < 4; ++nb) {
                const uint32_t eOff = (uint32_t)(nb * 16 * W2_PITCH);
                uint32_t bh[4], bl[4];
                ldsm_x4(bh[0], bh[1], bh[2], bh[3], bHiBase + eOff + kOff);
                ldsm_x4(bl[0], bl[1], bl[2], bl[3], bLoBase + eOff + kOff);
                mma16816(acc[2 * nb],     ah, bh[0], bh[1]);
                mma16816(acc[2 * nb + 1], ah, bh[2], bh[3]);
                mma16816(acc[2 * nb],     al, bh[0], bh[1]);
                mma16816(acc[2 * nb + 1], al, bh[2], bh[3]);
                mma16816(acc[2 * nb],     ah, bl[0], bl[1]);
                mma16816(acc[2 * nb + 1], ah, bl[2], bl[3]);
            }
        }
        if (c < 7) __syncthreads();   // A tile safe to overwrite
    }

    // ---- epilogue: + b2, direct coalesced stores ----
    {
        const int r1 = l >> 2;
        const int ec = (l & 3) * 2;
        const size_t rowA = ((size_t)(b * 256 + i0 + w) * 256 + j0 + r1);
        float* oA = out + rowA * 64;
        float* oB = oA + 8 * 64;       // r1 + 8 along j
#pragma unroll
        for (int nb = 0; nb < 8; ++nb) {
            const int e = nb * 8 + ec;
            const float2 bb = *(const float2*)(b2 + e);
            *(float2*)(oA + e) = make_float2(acc[nb][0] + bb.x, acc[nb][1] + bb.y);
            *(float2*)(oB + e) = make_float2(acc[nb][2] + bb.x, acc[nb][3] + bb.y);
        }
    }
}

// ---------------------------------------------------------------------------
// Launch
// ---------------------------------------------------------------------------
extern "C" void kernel_launch(void* const* d_in, const int* in_sizes, int n_in,
                              void* d_out, int out_size)
{
    (void)in_sizes; (void)n_in; (void)out_size;
    const float* x    = (const float*)d_in[0];
    const float* W_in = (const float*)d_in[1];
    const float* b_in = (const float*)d_in[2];
    const float* W1   = (const float*)d_in[3];
    const float* b1   = (const float*)d_in[4];
    const float* W2   = (const float*)d_in[5];
    const float* b2   = (const float*)d_in[6];
    float* out = (float*)d_out;

    float *hp = nullptr, *pabp = nullptr;
    __nv_bfloat16 *w2hip = nullptr, *w2lop = nullptr;
    cudaGetSymbolAddress((void**)&hp,    g_h);
    cudaGetSymbolAddress((void**)&pabp,  g_pab);
    cudaGetSymbolAddress((void**)&w2hip, g_W2hi);
    cudaGetSymbolAddress((void**)&w2lop, g_W2lo);

    gemm_nt_kernel<<<dim3(4, 16), 256>>>(x, W_in, b_in, hp,
                                         1024, 256, 256, 256, 0, 256);
    gemm_nt_kernel<<<dim3(8, 16), 256>>>(hp, W1, b1, pabp,
                                         1024, 512, 256, 512, 256, 256);
    w2split_kernel<<<64, 256>>>(W2, w2hip, w2lop);

    cudaFuncSetAttribute(edge_main_mma,
                         cudaFuncAttributeMaxDynamicSharedMemorySize, SMEM_TOTAL);
    edge_main_mma<<<dim3(32, 16, 4), 256, SMEM_TOTAL>>>(pabp, w2hip, w2lop,
                                                        b2, out);
}

// round 10
// speedup vs baseline: 1.8313x; 1.1106x over previous
#include <cuda_runtime.h>
#include <cuda_bf16.h>
#include <cstdint>
#include <cstddef>

// ---------------------------------------------------------------------------
// Scratch (no allocations allowed -> __device__ globals)
// ---------------------------------------------------------------------------
__device__ float g_h[1024 * 256];              // h = x @ W_in^T + b_in
__device__ float g_pab[1024 * 512];            // [pa | pb], b1 folded into pa
__device__ __nv_bfloat16 g_W2hi[64 * 256];     // bf16 split of W2, natural [e][g]
__device__ __nv_bfloat16 g_W2lo[64 * 256];

#define DINL __device__ __forceinline__

// ---------------------------------------------------------------------------
// PTX helpers (plain compute_103-safe: no tcgen05)
// ---------------------------------------------------------------------------
DINL uint32_t smem_u32(const void* p) {
    uint32_t a;
    asm("{ .reg .u64 t; cvta.to.shared.u64 t, %1; cvt.u32.u64 %0, t; }"
        : "=r"(a) : "l"(p));
    return a;
}
DINL void ldsm_x4(uint32_t& r0, uint32_t& r1, uint32_t& r2, uint32_t& r3,
                  uint32_t addr) {
    asm volatile("ldmatrix.sync.aligned.m8n8.x4.shared.b16 {%0,%1,%2,%3}, [%4];"
                 : "=r"(r0), "=r"(r1), "=r"(r2), "=r"(r3) : "r"(addr));
}
DINL void mma16816(float* c, const uint32_t* a, uint32_t b0, uint32_t b1) {
    asm volatile(
        "mma.sync.aligned.m16n8k16.row.col.f32.bf16.bf16.f32 "
        "{%0,%1,%2,%3}, {%4,%5,%6,%7}, {%8,%9}, {%0,%1,%2,%3};"
        : "+f"(c[0]), "+f"(c[1]), "+f"(c[2]), "+f"(c[3])
        : "r"(a[0]), "r"(a[1]), "r"(a[2]), "r"(a[3]), "r"(b0), "r"(b1));
}
DINL float silu_f(float z) {
    const float e = __expf(-z);
    return __fdividef(z, 1.0f + e);
}
DINL uint32_t pack_bf(__nv_bfloat16 a, __nv_bfloat16 b) {
    return (uint32_t)__bfloat16_as_ushort(a)
         | ((uint32_t)__bfloat16_as_ushort(b) << 16);
}
// split two fp32 into packed bf16 hi + residual lo fragments
DINL void split2(float x, float y, uint32_t& hi, uint32_t& lo) {
    const __nv_bfloat16 hx = __float2bfloat16(x);
    const __nv_bfloat16 hy = __float2bfloat16(y);
    hi = pack_bf(hx, hy);
    lo = pack_bf(__float2bfloat16(x - __bfloat162float(hx)),
                 __float2bfloat16(y - __bfloat162float(hy)));
}

// ---------------------------------------------------------------------------
// SMEM layout (bytes)
//   W2 tiles: [e][g] bf16, 64 rows x 512B data, pitch 528 (bank stride 4 mod 32)
//   pa/pb:    fp32 rows pitch 1040 B (260 floats, 4 mod 32)
// ---------------------------------------------------------------------------
static constexpr int W2_PITCH  = 528;
static constexpr int PAB_PITCH = 1040;
static constexpr int OFF_W2HI = 0;
static constexpr int OFF_W2LO = OFF_W2HI + 64 * W2_PITCH;     // 33792
static constexpr int OFF_PA   = OFF_W2LO + 64 * W2_PITCH;     // 67584 (8 rows)
static constexpr int OFF_PB   = OFF_PA + 8 * PAB_PITCH;       // 75904 (16 rows)
static constexpr int SMEM_TOTAL = OFF_PB + 16 * PAB_PITCH;    // 92544 B -> 2 CTAs/SM

// ---------------------------------------------------------------------------
// Prologue GEMM, templated on BM for full-chip CTA counts.
// C[m][n] = sum_k A[m*K+k] * B'[n][k] + (n<bias_n ? bias[n] : 0)
// B'[n][k] = B[(n & 255)*ldb + (n>>8)*hi_off + k]
// ---------------------------------------------------------------------------
template <int BM>
__global__ __launch_bounds__(256) void gemm_nt_kernel(
    const float* __restrict__ A, const float* __restrict__ B,
    const float* __restrict__ bias, float* __restrict__ C,
    int M, int N, int K, int ldb, int hi_off, int bias_n)
{
    __shared__ float As[BM][17];
    __shared__ float Bs[64][17];
    constexpr int MI = BM / 16;          // rows per thread
    const int t  = threadIdx.x;
    const int n0 = blockIdx.x * 64;
    const int m0 = blockIdx.y * BM;
    const int lr = t >> 2;               // load row
    const int lq = (t & 3) * 4;          // k-quad
    const int ty = t >> 4;               // 0..15
    const int tx = t & 15;               // 0..15

    float acc[MI][4];
#pragma unroll
    for (int i = 0; i < MI; ++i)
#pragma unroll
        for (int j = 0; j < 4; ++j) acc[i][j] = 0.0f;

    for (int k0 = 0; k0 < K; k0 += 16) {
        float4 av = make_float4(0.f, 0.f, 0.f, 0.f);
        const bool doA = (lr < BM);
        if (doA)
            av = *(const float4*)(A + (size_t)(m0 + lr) * K + k0 + lq);
        const int nr = n0 + lr;
        float4 bv = *(const float4*)(B + (size_t)(nr & 255) * ldb
                                       + (size_t)(nr >> 8) * hi_off + k0 + lq);
        __syncthreads();
        if (doA) {
            As[lr][lq + 0] = av.x; As[lr][lq + 1] = av.y;
            As[lr][lq + 2] = av.z; As[lr][lq + 3] = av.w;
        }
        Bs[lr][lq + 0] = bv.x; Bs[lr][lq + 1] = bv.y;
        Bs[lr][lq + 2] = bv.z; Bs[lr][lq + 3] = bv.w;
        __syncthreads();
#pragma unroll
        for (int k = 0; k < 16; ++k) {
            float a[MI], bb[4];
#pragma unroll
            for (int i = 0; i < MI; ++i) a[i] = As[ty * MI + i][k];
#pragma unroll
            for (int j = 0; j < 4; ++j) bb[j] = Bs[tx * 4 + j][k];
#pragma unroll
            for (int i = 0; i < MI; ++i)
#pragma unroll
                for (int j = 0; j < 4; ++j) acc[i][j] = fmaf(a[i], bb[j], acc[i][j]);
        }
    }
#pragma unroll
    for (int j = 0; j < 4; ++j) {
        const int n = n0 + tx * 4 + j;
        const float bz = (n < bias_n) ? bias[n] : 0.0f;
#pragma unroll
        for (int i = 0; i < MI; ++i)
            C[(size_t)(m0 + ty * MI + i) * N + n] = acc[i][j] + bz;
    }
}

// ---------------------------------------------------------------------------
// W2 hi/lo bf16 split (natural [e][g] layout)
// ---------------------------------------------------------------------------
__global__ void w2split_kernel(const float* __restrict__ W2,
                               __nv_bfloat16* __restrict__ hi,
                               __nv_bfloat16* __restrict__ lo)
{
    const int idx = blockIdx.x * 256 + threadIdx.x;   // 16384
    const float w = W2[idx];
    const __nv_bfloat16 h = __float2bfloat16(w);
    hi[idx] = h;
    lo[idx] = __float2bfloat16(w - __bfloat162float(h));
}

// ---------------------------------------------------------------------------
// Main fused kernel: SiLU -> A fragments built DIRECTLY in registers
// (no A smem tile, no in-loop barriers) -> mma.sync bf16 3-pass -> store.
// Per CTA: 128 pairs (8i x 16j) x 64 e, K=256 as 16 k16-slices.
// Warp w owns pairs [16w,16w+16): i = w fixed, m-row r = j_local.
// A[r][k] = silu(pa[w][k] + pb[r][k]).
// m16n8k16 A-fragment: a0=(r=l>>2, k=tig*2), a1=(r+8), a2=(k+8), a3=(r+8,k+8).
// ---------------------------------------------------------------------------
__global__ __launch_bounds__(256, 2) void edge_main_mma(
    const float* __restrict__ pab,
    const __nv_bfloat16* __restrict__ W2hi_g,
    const __nv_bfloat16* __restrict__ W2lo_g,
    const float* __restrict__ b2, float* __restrict__ out)
{
    extern __shared__ __align__(16) char smem[];
    const uint32_t sb = smem_u32(smem);
    const int t = threadIdx.x;
    const int w = t >> 5;
    const int l = t & 31;
    const int i0 = blockIdx.x * 8;
    const int j0 = blockIdx.y * 16;
    const int b  = blockIdx.z;

    // ---- stage W2 hi/lo into [e][g] pitch-528 tiles ----
    {
        const uint4* hs = (const uint4*)W2hi_g;   // 2048 uint4 each
        const uint4* ls = (const uint4*)W2lo_g;
#pragma unroll
        for (int i = 0; i < 8; ++i) {
            const int idx = t + i * 256;
            const int row = idx >> 5, c = idx & 31;
            *(uint4*)(smem + OFF_W2HI + row * W2_PITCH + c * 16) = hs[idx];
            *(uint4*)(smem + OFF_W2LO + row * W2_PITCH + c * 16) = ls[idx];
        }
    }
    // ---- stage pa (8 x 256 f32) and pb (16 x 256 f32) ----
#pragma unroll
    for (int i = 0; i < 2; ++i) {
        const int idx = t + i * 256, r = idx >> 6, c4 = idx & 63;
        ((float4*)(smem + OFF_PA + r * PAB_PITCH))[c4] =
            ((const float4*)(pab + (size_t)(b * 256 + i0 + r) * 512))[c4];
    }
#pragma unroll
    for (int i = 0; i < 4; ++i) {
        const int idx = t + i * 256, r = idx >> 6, c4 = idx & 63;
        ((float4*)(smem + OFF_PB + r * PAB_PITCH))[c4] =
            ((const float4*)(pab + (size_t)(b * 256 + j0 + r) * 512 + 256))[c4];
    }
    __syncthreads();   // the ONLY barrier

    const int grp = l >> 2;    // groupID 0..7 (m-row / output j-row)
    const int tig = l & 3;     // thread-in-group (k pair selector)

    const float* paW  = (const float*)(smem + OFF_PA + w * PAB_PITCH);
    const float* pbR0 = (const float*)(smem + OFF_PB + grp * PAB_PITCH);
    const float* pbR1 = (const float*)(smem + OFF_PB + (grp + 8) * PAB_PITCH);

    // B ldmatrix lane addressing (validated in R9):
    // x4 groups: (e0-7,kLo),(e0-7,kHi),(e8-15,kLo),(e8-15,kHi)
    const int lg = l >> 3;
    const uint32_t bRowPart =
        (uint32_t)(((lg >> 1) * 8 + (l & 7)) * W2_PITCH + (lg & 1) * 16);
    const uint32_t bHiBase = sb + OFF_W2HI + bRowPart;
    const uint32_t bLoBase = sb + OFF_W2LO + bRowPart;

    float acc[8][4];
#pragma unroll
    for (int n = 0; n < 8; ++n)
#pragma unroll
        for (int q = 0; q < 4; ++q) acc[n][q] = 0.0f;

#pragma unroll 4
    for (int s = 0; s < 16; ++s) {
        const int kb = s * 16 + tig * 2;
        // ---- gen 8 silu values = exactly this thread's A fragment ----
        const float2 paA  = *(const float2*)(paW  + kb);
        const float2 paB  = *(const float2*)(paW  + kb + 8);
        const float2 pb0A = *(const float2*)(pbR0 + kb);
        const float2 pb0B = *(const float2*)(pbR0 + kb + 8);
        const float2 pb1A = *(const float2*)(pbR1 + kb);
        const float2 pb1B = *(const float2*)(pbR1 + kb + 8);

        const float s00 = silu_f(paA.x + pb0A.x), s01 = silu_f(paA.y + pb0A.y);
        const float s10 = silu_f(paA.x + pb1A.x), s11 = silu_f(paA.y + pb1A.y);
        const float s02 = silu_f(paB.x + pb0B.x), s03 = silu_f(paB.y + pb0B.y);
        const float s12 = silu_f(paB.x + pb1B.x), s13 = silu_f(paB.y + pb1B.y);

        uint32_t ah[4], al[4];
        split2(s00, s01, ah[0], al[0]);   // a0: row grp,   k lo
        split2(s10, s11, ah[1], al[1]);   // a1: row grp+8, k lo
        split2(s02, s03, ah[2], al[2]);   // a2: row grp,   k hi
        split2(s12, s13, ah[3], al[3]);   // a3: row grp+8, k hi

        // ---- B loads + 24 MMAs (3-pass split) ----
        const uint32_t kOff = (uint32_t)(s * 32);
#pragma unroll
        for (int nbp = 0; nbp < 4; ++nbp) {
            const uint32_t eOff = (uint32_t)(nbp * 16 * W2_PITCH);
            uint32_t bh[4], bl[4];
            ldsm_x4(bh[0], bh[1], bh[2], bh[3], bHiBase + eOff + kOff);
            ldsm_x4(bl[0], bl[1], bl[2], bl[3], bLoBase + eOff + kOff);
            mma16816(acc[2 * nbp],     ah, bh[0], bh[1]);
            mma16816(acc[2 * nbp],     al, bh[0], bh[1]);
            mma16816(acc[2 * nbp],     ah, bl[0], bl[1]);
            mma16816(acc[2 * nbp + 1], ah, bh[2], bh[3]);
            mma16816(acc[2 * nbp + 1], al, bh[2], bh[3]);
            mma16816(acc[2 * nbp + 1], ah, bl[2], bl[3]);
        }
    }

    // ---- epilogue: + b2, direct coalesced stores ----
    {
        const int ec = tig * 2;
        const size_t rowA = ((size_t)(b * 256 + i0 + w) * 256 + j0 + grp);
        float* oA = out + rowA * 64;
        float* oB = oA + 8 * 64;       // grp + 8 along j
#pragma unroll
        for (int nb = 0; nb < 8; ++nb) {
            const int e = nb * 8 + ec;
            const float2 bb = *(const float2*)(b2 + e);
            *(float2*)(oA + e) = make_float2(acc[nb][0] + bb.x, acc[nb][1] + bb.y);
            *(float2*)(oB + e) = make_float2(acc[nb][2] + bb.x, acc[nb][3] + bb.y);
        }
    }
}

// ---------------------------------------------------------------------------
// Launch
// ---------------------------------------------------------------------------
extern "C" void kernel_launch(void* const* d_in, const int* in_sizes, int n_in,
                              void* d_out, int out_size)
{
    (void)in_sizes; (void)n_in; (void)out_size;
    const float* x    = (const float*)d_in[0];
    const float* W_in = (const float*)d_in[1];
    const float* b_in = (const float*)d_in[2];
    const float* W1   = (const float*)d_in[3];
    const float* b1   = (const float*)d_in[4];
    const float* W2   = (const float*)d_in[5];
    const float* b2   = (const float*)d_in[6];
    float* out = (float*)d_out;

    float *hp = nullptr, *pabp = nullptr;
    __nv_bfloat16 *w2hip = nullptr, *w2lop = nullptr;
    cudaGetSymbolAddress((void**)&hp,    g_h);
    cudaGetSymbolAddress((void**)&pabp,  g_pab);
    cudaGetSymbolAddress((void**)&w2hip, g_W2hi);
    cudaGetSymbolAddress((void**)&w2lop, g_W2lo);

    // h = x @ W_in^T + b_in          (128 CTAs)
    gemm_nt_kernel<32><<<dim3(4, 32), 256>>>(x, W_in, b_in, hp,
                                             1024, 256, 256, 256, 0, 256);
    // [pa | pb] = h @ [Wa^T | Wb^T]  (256 CTAs), b1 folded into pa
    gemm_nt_kernel<32><<<dim3(8, 32), 256>>>(hp, W1, b1, pabp,
                                             1024, 512, 256, 512, 256, 256);
    w2split_kernel<<<64, 256>>>(W2, w2hip, w2lop);

    cudaFuncSetAttribute(edge_main_mma,
                         cudaFuncAttributeMaxDynamicSharedMemorySize, SMEM_TOTAL);
    edge_main_mma<<<dim3(32, 16, 4), 256, SMEM_TOTAL>>>(pabp, w2hip, w2lop,
                                                        b2, out);
}

// round 11
// speedup vs baseline: 1.8776x; 1.0253x over previous
#include <cuda_runtime.h>
#include <cuda_bf16.h>
#include <cstdint>
#include <cstddef>

// ---------------------------------------------------------------------------
// Scratch (no allocations allowed -> __device__ globals)
// ---------------------------------------------------------------------------
__device__ float g_h[1024 * 256];              // h = x @ W_in^T + b_in
__device__ float g_pab[1024 * 512];            // [pa | pb], b1 folded into pa
__device__ __nv_bfloat16 g_W2hi[64 * 256];     // bf16 split of W2, natural [e][g]
__device__ __nv_bfloat16 g_W2lo[64 * 256];

#define DINL __device__ __forceinline__

// ---------------------------------------------------------------------------
// PTX helpers (plain compute_103-safe: no tcgen05)
// ---------------------------------------------------------------------------
DINL uint32_t smem_u32(const void* p) {
    uint32_t a;
    asm("{ .reg .u64 t; cvta.to.shared.u64 t, %1; cvt.u32.u64 %0, t; }"
        : "=r"(a) : "l"(p));
    return a;
}
DINL void ldsm_x4(uint32_t& r0, uint32_t& r1, uint32_t& r2, uint32_t& r3,
                  uint32_t addr) {
    asm volatile("ldmatrix.sync.aligned.m8n8.x4.shared.b16 {%0,%1,%2,%3}, [%4];"
                 : "=r"(r0), "=r"(r1), "=r"(r2), "=r"(r3) : "r"(addr));
}
DINL void mma16816(float* c, const uint32_t* a, uint32_t b0, uint32_t b1) {
    asm volatile(
        "mma.sync.aligned.m16n8k16.row.col.f32.bf16.bf16.f32 "
        "{%0,%1,%2,%3}, {%4,%5,%6,%7}, {%8,%9}, {%0,%1,%2,%3};"
        : "+f"(c[0]), "+f"(c[1]), "+f"(c[2]), "+f"(c[3])
        : "r"(a[0]), "r"(a[1]), "r"(a[2]), "r"(a[3]), "r"(b0), "r"(b1));
}
DINL float silu_f(float z) {
    const float e = __expf(-z);
    return __fdividef(z, 1.0f + e);
}
DINL uint32_t pack_bf(__nv_bfloat16 a, __nv_bfloat16 b) {
    return (uint32_t)__bfloat16_as_ushort(a)
         | ((uint32_t)__bfloat16_as_ushort(b) << 16);
}
// split two fp32 into packed bf16 hi + residual lo fragments
DINL void split2(float x, float y, uint32_t& hi, uint32_t& lo) {
    const __nv_bfloat16 hx = __float2bfloat16(x);
    const __nv_bfloat16 hy = __float2bfloat16(y);
    hi = pack_bf(hx, hy);
    lo = pack_bf(__float2bfloat16(x - __bfloat162float(hx)),
                 __float2bfloat16(y - __bfloat162float(hy)));
}

// ---------------------------------------------------------------------------
// SMEM layout (bytes)
//   W2 tiles: [e][g] bf16, 64 rows x 512B data, pitch 528 (bank stride 4 mod 32)
//   pa/pb:    fp32 rows pitch 1040 B (260 floats, bank stride 4 mod 32)
// ---------------------------------------------------------------------------
static constexpr int W2_PITCH  = 528;
static constexpr int PAB_PITCH = 1040;
static constexpr int OFF_W2HI = 0;
static constexpr int OFF_W2LO = OFF_W2HI + 64 * W2_PITCH;     // 33792
static constexpr int OFF_PA   = OFF_W2LO + 64 * W2_PITCH;     // 67584 (16 rows)
static constexpr int OFF_PB   = OFF_PA + 16 * PAB_PITCH;      // 84224 (16 rows)
static constexpr int SMEM_TOTAL = OFF_PB + 16 * PAB_PITCH;    // 100864 B -> 2 CTAs/SM

// ---------------------------------------------------------------------------
// Prologue GEMM (validated), templated on BM for full-chip CTA counts.
// C[m][n] = sum_k A[m*K+k] * B'[n][k] + (n<bias_n ? bias[n] : 0)
// B'[n][k] = B[(n & 255)*ldb + (n>>8)*hi_off + k]
// ---------------------------------------------------------------------------
template <int BM>
__global__ __launch_bounds__(256) void gemm_nt_kernel(
    const float* __restrict__ A, const float* __restrict__ B,
    const float* __restrict__ bias, float* __restrict__ C,
    int M, int N, int K, int ldb, int hi_off, int bias_n)
{
    __shared__ float As[BM][17];
    __shared__ float Bs[64][17];
    constexpr int MI = BM / 16;
    const int t  = threadIdx.x;
    const int n0 = blockIdx.x * 64;
    const int m0 = blockIdx.y * BM;
    const int lr = t >> 2;
    const int lq = (t & 3) * 4;
    const int ty = t >> 4;
    const int tx = t & 15;

    float acc[MI][4];
#pragma unroll
    for (int i = 0; i < MI; ++i)
#pragma unroll
        for (int j = 0; j < 4; ++j) acc[i][j] = 0.0f;

    for (int k0 = 0; k0 < K; k0 += 16) {
        float4 av = make_float4(0.f, 0.f, 0.f, 0.f);
        const bool doA = (lr < BM);
        if (doA)
            av = *(const float4*)(A + (size_t)(m0 + lr) * K + k0 + lq);
        const int nr = n0 + lr;
        float4 bv = *(const float4*)(B + (size_t)(nr & 255) * ldb
                                       + (size_t)(nr >> 8) * hi_off + k0 + lq);
        __syncthreads();
        if (doA) {
            As[lr][lq + 0] = av.x; As[lr][lq + 1] = av.y;
            As[lr][lq + 2] = av.z; As[lr][lq + 3] = av.w;
        }
        Bs[lr][lq + 0] = bv.x; Bs[lr][lq + 1] = bv.y;
        Bs[lr][lq + 2] = bv.z; Bs[lr][lq + 3] = bv.w;
        __syncthreads();
#pragma unroll
        for (int k = 0; k < 16; ++k) {
            float a[MI], bb[4];
#pragma unroll
            for (int i = 0; i < MI; ++i) a[i] = As[ty * MI + i][k];
#pragma unroll
            for (int j = 0; j < 4; ++j) bb[j] = Bs[tx * 4 + j][k];
#pragma unroll
            for (int i = 0; i < MI; ++i)
#pragma unroll
                for (int j = 0; j < 4; ++j) acc[i][j] = fmaf(a[i], bb[j], acc[i][j]);
        }
    }
#pragma unroll
    for (int j = 0; j < 4; ++j) {
        const int n = n0 + tx * 4 + j;
        const float bz = (n < bias_n) ? bias[n] : 0.0f;
#pragma unroll
        for (int i = 0; i < MI; ++i)
            C[(size_t)(m0 + ty * MI + i) * N + n] = acc[i][j] + bz;
    }
}

// ---------------------------------------------------------------------------
// W2 hi/lo bf16 split (natural [e][g] layout)
// ---------------------------------------------------------------------------
__global__ void w2split_kernel(const float* __restrict__ W2,
                               __nv_bfloat16* __restrict__ hi,
                               __nv_bfloat16* __restrict__ lo)
{
    const int idx = blockIdx.x * 256 + threadIdx.x;   // 16384
    const float w = W2[idx];
    const __nv_bfloat16 h = __float2bfloat16(w);
    hi[idx] = h;
    lo[idx] = __float2bfloat16(w - __bfloat162float(h));
}

// ---------------------------------------------------------------------------
// Main fused kernel, m32-per-warp variant.
// Per CTA: 512 pairs (16 i x 16 j) x 64 e, K=256 as 16 k16-slices.
// Warp w owns TWO m16 tiles: i = i0+w and i = i0+w+8 (same 16 j's), so each
// B-fragment pair (bh,bl) feeds 12 MMAs; pb gen-loads shared across m-tiles.
// A[r][k] = silu(pa[i][k] + pb[r][k]);
// m16n8k16 A-frag: a0=(r=l>>2, k=tig*2), a1=(r+8), a2=(k+8), a3=(r+8,k+8).
// ---------------------------------------------------------------------------
__global__ __launch_bounds__(256, 2) void edge_main_mma(
    const float* __restrict__ pab,
    const __nv_bfloat16* __restrict__ W2hi_g,
    const __nv_bfloat16* __restrict__ W2lo_g,
    const float* __restrict__ b2, float* __restrict__ out)
{
    extern __shared__ __align__(16) char smem[];
    const uint32_t sb = smem_u32(smem);
    const int t = threadIdx.x;
    const int w = t >> 5;
    const int l = t & 31;
    const int i0 = blockIdx.x * 16;
    const int j0 = blockIdx.y * 16;
    const int b  = blockIdx.z;

    // ---- stage W2 hi/lo into [e][g] pitch-528 tiles ----
    {
        const uint4* hs = (const uint4*)W2hi_g;   // 2048 uint4 each
        const uint4* ls = (const uint4*)W2lo_g;
#pragma unroll
        for (int i = 0; i < 8; ++i) {
            const int idx = t + i * 256;
            const int row = idx >> 5, c = idx & 31;
            *(uint4*)(smem + OFF_W2HI + row * W2_PITCH + c * 16) = hs[idx];
            *(uint4*)(smem + OFF_W2LO + row * W2_PITCH + c * 16) = ls[idx];
        }
    }
    // ---- stage pa (16 x 256 f32) and pb (16 x 256 f32) ----
#pragma unroll
    for (int i = 0; i < 4; ++i) {
        const int idx = t + i * 256, r = idx >> 6, c4 = idx & 63;
        ((float4*)(smem + OFF_PA + r * PAB_PITCH))[c4] =
            ((const float4*)(pab + (size_t)(b * 256 + i0 + r) * 512))[c4];
    }
#pragma unroll
    for (int i = 0; i < 4; ++i) {
        const int idx = t + i * 256, r = idx >> 6, c4 = idx & 63;
        ((float4*)(smem + OFF_PB + r * PAB_PITCH))[c4] =
            ((const float4*)(pab + (size_t)(b * 256 + j0 + r) * 512 + 256))[c4];
    }
    __syncthreads();   // the ONLY barrier

    const int grp = l >> 2;    // 0..7 (m-row within tile / output j-row)
    const int tig = l & 3;     // thread-in-group (k pair selector)

    const float* paW0 = (const float*)(smem + OFF_PA + w * PAB_PITCH);
    const float* paW1 = (const float*)(smem + OFF_PA + (w + 8) * PAB_PITCH);
    const float* pbR0 = (const float*)(smem + OFF_PB + grp * PAB_PITCH);
    const float* pbR1 = (const float*)(smem + OFF_PB + (grp + 8) * PAB_PITCH);

    // B ldmatrix lane addressing (validated R9/R10):
    // x4 groups: (e0-7,kLo),(e0-7,kHi),(e8-15,kLo),(e8-15,kHi)
    const int lg = l >> 3;
    const uint32_t bRowPart =
        (uint32_t)(((lg >> 1) * 8 + (l & 7)) * W2_PITCH + (lg & 1) * 16);
    const uint32_t bHiBase = sb + OFF_W2HI + bRowPart;
    const uint32_t bLoBase = sb + OFF_W2LO + bRowPart;

    float acc0[8][4], acc1[8][4];
#pragma unroll
    for (int n = 0; n < 8; ++n)
#pragma unroll
        for (int q = 0; q < 4; ++q) { acc0[n][q] = 0.0f; acc1[n][q] = 0.0f; }

#pragma unroll 2
    for (int s = 0; s < 16; ++s) {
        const int kb = s * 16 + tig * 2;
        // ---- shared pb loads (reused by both m-tiles) ----
        const float2 pb0A = *(const float2*)(pbR0 + kb);
        const float2 pb0B = *(const float2*)(pbR0 + kb + 8);
        const float2 pb1A = *(const float2*)(pbR1 + kb);
        const float2 pb1B = *(const float2*)(pbR1 + kb + 8);

        uint32_t ah0[4], al0[4], ah1[4], al1[4];
        {   // m-tile 0: i = i0 + w
            const float2 paA = *(const float2*)(paW0 + kb);
            const float2 paB = *(const float2*)(paW0 + kb + 8);
            split2(silu_f(paA.x + pb0A.x), silu_f(paA.y + pb0A.y), ah0[0], al0[0]);
            split2(silu_f(paA.x + pb1A.x), silu_f(paA.y + pb1A.y), ah0[1], al0[1]);
            split2(silu_f(paB.x + pb0B.x), silu_f(paB.y + pb0B.y), ah0[2], al0[2]);
            split2(silu_f(paB.x + pb1B.x), silu_f(paB.y + pb1B.y), ah0[3], al0[3]);
        }
        {   // m-tile 1: i = i0 + w + 8
            const float2 paA = *(const float2*)(paW1 + kb);
            const float2 paB = *(const float2*)(paW1 + kb + 8);
            split2(silu_f(paA.x + pb0A.x), silu_f(paA.y + pb0A.y), ah1[0], al1[0]);
            split2(silu_f(paA.x + pb1A.x), silu_f(paA.y + pb1A.y), ah1[1], al1[1]);
            split2(silu_f(paB.x + pb0B.x), silu_f(paB.y + pb0B.y), ah1[2], al1[2]);
            split2(silu_f(paB.x + pb1B.x), silu_f(paB.y + pb1B.y), ah1[3], al1[3]);
        }

        // ---- B loads + 48 MMAs (3-pass split x 2 m-tiles) ----
        const uint32_t kOff = (uint32_t)(s * 32);
#pragma unroll
        for (int nbp = 0; nbp < 4; ++nbp) {
            const uint32_t eOff = (uint32_t)(nbp * 16 * W2_PITCH);
            uint32_t bh[4], bl[4];
            ldsm_x4(bh[0], bh[1], bh[2], bh[3], bHiBase + eOff + kOff);
            ldsm_x4(bl[0], bl[1], bl[2], bl[3], bLoBase + eOff + kOff);
            mma16816(acc0[2 * nbp],     ah0, bh[0], bh[1]);
            mma16816(acc0[2 * nbp],     al0, bh[0], bh[1]);
            mma16816(acc0[2 * nbp],     ah0, bl[0], bl[1]);
            mma16816(acc0[2 * nbp + 1], ah0, bh[2], bh[3]);
            mma16816(acc0[2 * nbp + 1], al0, bh[2], bh[3]);
            mma16816(acc0[2 * nbp + 1], ah0, bl[2], bl[3]);
            mma16816(acc1[2 * nbp],     ah1, bh[0], bh[1]);
            mma16816(acc1[2 * nbp],     al1, bh[0], bh[1]);
            mma16816(acc1[2 * nbp],     ah1, bl[0], bl[1]);
            mma16816(acc1[2 * nbp + 1], ah1, bh[2], bh[3]);
            mma16816(acc1[2 * nbp + 1], al1, bh[2], bh[3]);
            mma16816(acc1[2 * nbp + 1], ah1, bl[2], bl[3]);
        }
    }

    // ---- epilogue: + b2, direct coalesced stores (4 output rows/thread) ----
    {
        const int ec = tig * 2;
        const size_t row0 = ((size_t)(b * 256 + i0 + w) * 256 + j0 + grp);
        const size_t row1 = ((size_t)(b * 256 + i0 + w + 8) * 256 + j0 + grp);
        float* o0A = out + row0 * 64;
        float* o0B = o0A + 8 * 64;     // grp + 8 along j
        float* o1A = out + row1 * 64;
        float* o1B = o1A + 8 * 64;
#pragma unroll
        for (int nb = 0; nb < 8; ++nb) {
            const int e = nb * 8 + ec;
            const float2 bb = *(const float2*)(b2 + e);
            *(float2*)(o0A + e) = make_float2(acc0[nb][0] + bb.x, acc0[nb][1] + bb.y);
            *(float2*)(o0B + e) = make_float2(acc0[nb][2] + bb.x, acc0[nb][3] + bb.y);
            *(float2*)(o1A + e) = make_float2(acc1[nb][0] + bb.x, acc1[nb][1] + bb.y);
            *(float2*)(o1B + e) = make_float2(acc1[nb][2] + bb.x, acc1[nb][3] + bb.y);
        }
    }
}

// ---------------------------------------------------------------------------
// Launch
// ---------------------------------------------------------------------------
extern "C" void kernel_launch(void* const* d_in, const int* in_sizes, int n_in,
                              void* d_out, int out_size)
{
    (void)in_sizes; (void)n_in; (void)out_size;
    const float* x    = (const float*)d_in[0];
    const float* W_in = (const float*)d_in[1];
    const float* b_in = (const float*)d_in[2];
    const float* W1   = (const float*)d_in[3];
    const float* b1   = (const float*)d_in[4];
    const float* W2   = (const float*)d_in[5];
    const float* b2   = (const float*)d_in[6];
    float* out = (float*)d_out;

    float *hp = nullptr, *pabp = nullptr;
    __nv_bfloat16 *w2hip = nullptr, *w2lop = nullptr;
    cudaGetSymbolAddress((void**)&hp,    g_h);
    cudaGetSymbolAddress((void**)&pabp,  g_pab);
    cudaGetSymbolAddress((void**)&w2hip, g_W2hi);
    cudaGetSymbolAddress((void**)&w2lop, g_W2lo);

    // h = x @ W_in^T + b_in          (128 CTAs)
    gemm_nt_kernel<32><<<dim3(4, 32), 256>>>(x, W_in, b_in, hp,
                                             1024, 256, 256, 256, 0, 256);
    // [pa | pb] = h @ [Wa^T | Wb^T]  (256 CTAs), b1 folded into pa
    gemm_nt_kernel<32><<<dim3(8, 32), 256>>>(hp, W1, b1, pabp,
                                             1024, 512, 256, 512, 256, 256);
    w2split_kernel<<<64, 256>>>(W2, w2hip, w2lop);

    cudaFuncSetAttribute(edge_main_mma,
                         cudaFuncAttributeMaxDynamicSharedMemorySize, SMEM_TOTAL);
    edge_main_mma<<<dim3(16, 16, 4), 256, SMEM_TOTAL>>>(pabp, w2hip, w2lop,
                                                        b2, out);
}